// round 1
// baseline (speedup 1.0000x reference)
#include <cuda_runtime.h>
#include <math.h>
#include <stdint.h>

#define EMBED   1024
#define NHEADS  16
#define HDIM    64
#define BATCH   2
#define SEQ     2048
#define MTOT    (BATCH*SEQ)

// ---------------- scratch (static device globals: allocation-guard legal) ---
__device__ float g_Q[(size_t)BATCH*NHEADS*SEQ*HDIM];
__device__ float g_K[(size_t)BATCH*NHEADS*SEQ*HDIM];
__device__ float g_V[(size_t)BATCH*NHEADS*SEQ*HDIM];

// ---------------- helpers ---------------------------------------------------
__device__ __forceinline__ unsigned f2tf(float f) {
    unsigned u;
    asm("cvt.rna.tf32.f32 %0, %1;" : "=r"(u) : "f"(f));
    return u;
}

// D = A(16x8,row) * B(8x8,col) + D   (tf32 inputs, f32 accum)
__device__ __forceinline__ void mma8(float* c, const unsigned* a, const unsigned* b) {
    asm volatile(
        "mma.sync.aligned.m16n8k8.row.col.f32.tf32.tf32.f32 "
        "{%0,%1,%2,%3},{%4,%5,%6,%7},{%8,%9},{%0,%1,%2,%3};\n"
        : "+f"(c[0]), "+f"(c[1]), "+f"(c[2]), "+f"(c[3])
        : "r"(a[0]), "r"(a[1]), "r"(a[2]), "r"(a[3]), "r"(b[0]), "r"(b[1]));
}

// robust scalar read: int32 / int64 low word / float32 / float64
__device__ __forceinline__ float load_scale(const void* p) {
    int iv = *(const int*)p;
    if (iv > 0 && iv < (1 << 20)) return (float)iv;
    float f = __int_as_float(iv);
    if (f > 1e-6f && f < 1e6f) return f;
    return (float)(*(const double*)p);
}

// ---------------- QKV projection GEMM ---------------------------------------
// Y = X @ W + b, written scattered into [b,h,s,d] layout.
#define BM   128
#define BN   128
#define BKK  32
#define ASTR 36    // (gid*36 + tig) % 32 = gid*4+tig  -> conflict-free A frags
#define BSTR 136   // (tig*136 + gid) % 32 = tig*8+gid -> conflict-free B frags

__global__ void __launch_bounds__(256, 2) qkv_gemm(
    const float* __restrict__ X,
    const float* __restrict__ Wq, const float* __restrict__ bq,
    const float* __restrict__ Wk, const float* __restrict__ bk,
    const float* __restrict__ Wv, const float* __restrict__ bv)
{
    __shared__ unsigned As[BM * ASTR];
    __shared__ unsigned Bs[BKK * BSTR];

    const float* W;
    const float* bias;
    float* Out;
    if (blockIdx.z == 0)      { W = Wq; bias = bq; Out = g_Q; }
    else if (blockIdx.z == 1) { W = Wk; bias = bk; Out = g_K; }
    else                      { W = Wv; bias = bv; Out = g_V; }

    const int tid  = threadIdx.x;
    const int lane = tid & 31, warp = tid >> 5;
    const int gid  = lane >> 2, tig = lane & 3;
    const int wm   = (warp >> 2) * 64;   // warp rows: 2 x 64
    const int wn   = (warp & 3) * 32;    // warp cols: 4 x 32
    const int mBase = blockIdx.y * BM;
    const int nBase = blockIdx.x * BN;

    float acc[4][4][4];
#pragma unroll
    for (int mt = 0; mt < 4; mt++)
#pragma unroll
        for (int nt = 0; nt < 4; nt++)
#pragma unroll
            for (int j = 0; j < 4; j++) acc[mt][nt][j] = 0.f;

    for (int kk = 0; kk < EMBED; kk += BKK) {
        // A tile: 128x32 (x), convert to tf32 in smem
#pragma unroll
        for (int i = 0; i < 4; i++) {
            int idx = tid + i * 256;           // 0..1023 float4s
            int r = idx >> 3, c = (idx & 7) * 4;
            float4 v = *(const float4*)(X + (size_t)(mBase + r) * EMBED + kk + c);
            unsigned* d = As + r * ASTR + c;
            d[0] = f2tf(v.x); d[1] = f2tf(v.y); d[2] = f2tf(v.z); d[3] = f2tf(v.w);
        }
        // B tile: 32x128 (W rows kk..kk+31)
#pragma unroll
        for (int i = 0; i < 4; i++) {
            int idx = tid + i * 256;
            int r = idx >> 5, c = (idx & 31) * 4;
            float4 v = *(const float4*)(W + (size_t)(kk + r) * EMBED + nBase + c);
            unsigned* d = Bs + r * BSTR + c;
            d[0] = f2tf(v.x); d[1] = f2tf(v.y); d[2] = f2tf(v.z); d[3] = f2tf(v.w);
        }
        __syncthreads();

#pragma unroll
        for (int ks = 0; ks < BKK; ks += 8) {
            unsigned a[4][4], bf[4][2];
#pragma unroll
            for (int mt = 0; mt < 4; mt++) {
                int r0 = wm + mt * 16;
                a[mt][0] = As[(r0 + gid)     * ASTR + ks + tig];
                a[mt][1] = As[(r0 + gid + 8) * ASTR + ks + tig];
                a[mt][2] = As[(r0 + gid)     * ASTR + ks + tig + 4];
                a[mt][3] = As[(r0 + gid + 8) * ASTR + ks + tig + 4];
            }
#pragma unroll
            for (int nt = 0; nt < 4; nt++) {
                int c0 = wn + nt * 8;
                bf[nt][0] = Bs[(ks + tig)     * BSTR + c0 + gid];
                bf[nt][1] = Bs[(ks + tig + 4) * BSTR + c0 + gid];
            }
#pragma unroll
            for (int mt = 0; mt < 4; mt++)
#pragma unroll
                for (int nt = 0; nt < 4; nt++)
                    mma8(acc[mt][nt], a[mt], bf[nt]);
        }
        __syncthreads();
    }

    // epilogue: bias + scatter into [b,h,s,d]
#pragma unroll
    for (int nt = 0; nt < 4; nt++) {
        int c0 = nBase + wn + nt * 8 + 2 * tig;
        float b0 = bias[c0], b1 = bias[c0 + 1];
        int h = c0 >> 6, d = c0 & 63;
#pragma unroll
        for (int mt = 0; mt < 4; mt++) {
#pragma unroll
            for (int rr = 0; rr < 2; rr++) {
                int r = mBase + wm + mt * 16 + gid + rr * 8;
                int bi = r >> 11, s = r & (SEQ - 1);
                float* op = Out + (((size_t)(bi * NHEADS + h) * SEQ + s) * HDIM) + d;
                op[0] = acc[mt][nt][rr * 2 + 0] + b0;
                op[1] = acc[mt][nt][rr * 2 + 1] + b1;
            }
        }
    }
}

// ---------------- flash attention --------------------------------------------
#define SSTR 72      // tile stride: conflict-free for all fragment patterns
#define ATTN_SMEM_WORDS (4 * 64 * SSTR + 4 * 64)
#define ATTN_SMEM_BYTES (ATTN_SMEM_WORDS * 4)

__global__ void __launch_bounds__(256) attn_kernel(
    const int* __restrict__ maskg, const void* __restrict__ scale_ptr,
    float* __restrict__ out)
{
    extern __shared__ unsigned smem_u[];
    unsigned* Qs = smem_u;
    unsigned* Ks = Qs + 64 * SSTR;
    unsigned* Vs = Ks + 64 * SSTR;
    float*    Ps = (float*)(Vs + 64 * SSTR);
    unsigned* Pu = (unsigned*)Ps;
    float* m_s     = Ps + 64 * SSTR;
    float* l_s     = m_s + 64;
    float* alpha_s = l_s + 64;
    int*   mask_s  = (int*)(alpha_s + 64);

    const int tid  = threadIdx.x;
    const int lane = tid & 31, warp = tid >> 5;
    const int gid  = lane >> 2, tig = lane & 3;
    const int wm   = (warp & 3) * 16;   // 4 warp rows x 16
    const int wn   = (warp >> 2) * 32;  // 2 warp cols x 32

    const int bh = blockIdx.y;
    const int b  = bh >> 4;
    const int q0 = blockIdx.x * 64;

    const float* Qg = g_Q + (size_t)bh * SEQ * HDIM;
    const float* Kg = g_K + (size_t)bh * SEQ * HDIM;
    const float* Vg = g_V + (size_t)bh * SEQ * HDIM;

    const float rscale = 1.0f / load_scale(scale_ptr);

    // load Q tile once (64 x 64), tf32
#pragma unroll
    for (int i = 0; i < 4; i++) {
        int idx = tid + i * 256;
        int r = idx >> 4, c = (idx & 15) * 4;
        float4 v = *(const float4*)(Qg + (size_t)(q0 + r) * HDIM + c);
        unsigned* d = Qs + r * SSTR + c;
        d[0] = f2tf(v.x); d[1] = f2tf(v.y); d[2] = f2tf(v.z); d[3] = f2tf(v.w);
    }
    if (tid < 64) { m_s[tid] = -INFINITY; l_s[tid] = 0.f; }

    float o[4][4];
#pragma unroll
    for (int nt = 0; nt < 4; nt++)
#pragma unroll
        for (int j = 0; j < 4; j++) o[nt][j] = 0.f;

    __syncthreads();

    for (int kt = 0; kt < SEQ; kt += 64) {
        // load K, V tiles + mask slice
#pragma unroll
        for (int i = 0; i < 4; i++) {
            int idx = tid + i * 256;
            int r = idx >> 4, c = (idx & 15) * 4;
            float4 kv = *(const float4*)(Kg + (size_t)(kt + r) * HDIM + c);
            unsigned* dk = Ks + r * SSTR + c;
            dk[0] = f2tf(kv.x); dk[1] = f2tf(kv.y); dk[2] = f2tf(kv.z); dk[3] = f2tf(kv.w);
            float4 vv = *(const float4*)(Vg + (size_t)(kt + r) * HDIM + c);
            unsigned* dv = Vs + r * SSTR + c;
            dv[0] = f2tf(vv.x); dv[1] = f2tf(vv.y); dv[2] = f2tf(vv.z); dv[3] = f2tf(vv.w);
        }
        if (tid < 64) mask_s[tid] = maskg[b * SEQ + kt + tid];
        __syncthreads();

        // S = Q @ K^T  (each warp: 16 x 32)
        float sacc[4][4];
#pragma unroll
        for (int nt = 0; nt < 4; nt++)
#pragma unroll
            for (int j = 0; j < 4; j++) sacc[nt][j] = 0.f;

#pragma unroll
        for (int ks = 0; ks < 64; ks += 8) {
            unsigned a[4];
            a[0] = Qs[(wm + gid)     * SSTR + ks + tig];
            a[1] = Qs[(wm + gid + 8) * SSTR + ks + tig];
            a[2] = Qs[(wm + gid)     * SSTR + ks + tig + 4];
            a[3] = Qs[(wm + gid + 8) * SSTR + ks + tig + 4];
#pragma unroll
            for (int nt = 0; nt < 4; nt++) {
                int c0 = wn + nt * 8;
                unsigned bf[2];
                bf[0] = Ks[(c0 + gid) * SSTR + ks + tig];
                bf[1] = Ks[(c0 + gid) * SSTR + ks + tig + 4];
                mma8(sacc[nt], a, bf);
            }
        }

        // scale + mask -> Ps (f32)
#pragma unroll
        for (int nt = 0; nt < 4; nt++) {
            int cc = wn + nt * 8 + 2 * tig;
            int rr = wm + gid;
            bool k0 = mask_s[cc] != 0;
            bool k1 = mask_s[cc + 1] != 0;
            Ps[rr * SSTR + cc]           = k0 ? sacc[nt][0] * rscale : -1e30f;
            Ps[rr * SSTR + cc + 1]       = k1 ? sacc[nt][1] * rscale : -1e30f;
            Ps[(rr + 8) * SSTR + cc]     = k0 ? sacc[nt][2] * rscale : -1e30f;
            Ps[(rr + 8) * SSTR + cc + 1] = k1 ? sacc[nt][3] * rscale : -1e30f;
        }
        __syncthreads();

        // online softmax update (4 threads per row, in-warp groups)
        {
            int row = tid >> 2, part = tid & 3;
            const float* prow = Ps + row * SSTR + part * 16;
            float lm = prow[0];
#pragma unroll
            for (int j = 1; j < 16; j++) lm = fmaxf(lm, prow[j]);
            lm = fmaxf(lm, __shfl_xor_sync(0xffffffffu, lm, 1));
            lm = fmaxf(lm, __shfl_xor_sync(0xffffffffu, lm, 2));
            float m_old = m_s[row];
            float m_new = fmaxf(m_old, lm);
            float lsum = 0.f;
            unsigned* purow = Pu + row * SSTR + part * 16;
#pragma unroll
            for (int j = 0; j < 16; j++) {
                float p = expf(prow[j] - m_new);
                lsum += p;
                purow[j] = f2tf(p);
            }
            lsum += __shfl_xor_sync(0xffffffffu, lsum, 1);
            lsum += __shfl_xor_sync(0xffffffffu, lsum, 2);
            if (part == 0) {
                float alpha = expf(m_old - m_new);
                alpha_s[row] = alpha;
                l_s[row] = l_s[row] * alpha + lsum;
                m_s[row] = m_new;
            }
        }
        __syncthreads();

        // rescale O, then O += P @ V
        {
            float a0 = alpha_s[wm + gid];
            float a1 = alpha_s[wm + gid + 8];
#pragma unroll
            for (int nt = 0; nt < 4; nt++) {
                o[nt][0] *= a0; o[nt][1] *= a0; o[nt][2] *= a1; o[nt][3] *= a1;
            }
        }
#pragma unroll
        for (int ks = 0; ks < 64; ks += 8) {
            unsigned a[4];
            a[0] = Pu[(wm + gid)     * SSTR + ks + tig];
            a[1] = Pu[(wm + gid + 8) * SSTR + ks + tig];
            a[2] = Pu[(wm + gid)     * SSTR + ks + tig + 4];
            a[3] = Pu[(wm + gid + 8) * SSTR + ks + tig + 4];
#pragma unroll
            for (int nt = 0; nt < 4; nt++) {
                int c0 = wn + nt * 8;
                unsigned bf[2];
                bf[0] = Vs[(ks + tig)     * SSTR + c0 + gid];
                bf[1] = Vs[(ks + tig + 4) * SSTR + c0 + gid];
                mma8(o[nt], a, bf);
            }
        }
        __syncthreads();
    }

    // epilogue: O / l -> out [b,h,s,d]
    float li0 = 1.f / l_s[wm + gid];
    float li1 = 1.f / l_s[wm + gid + 8];
#pragma unroll
    for (int nt = 0; nt < 4; nt++) {
        int cc = wn + nt * 8 + 2 * tig;
        size_t base = ((size_t)bh * SEQ + q0 + wm + gid) * HDIM + cc;
        out[base]     = o[nt][0] * li0;
        out[base + 1] = o[nt][1] * li0;
        size_t base2 = base + (size_t)8 * HDIM;
        out[base2]     = o[nt][2] * li1;
        out[base2 + 1] = o[nt][3] * li1;
    }
}

// ---------------- launcher ----------------------------------------------------
extern "C" void kernel_launch(void* const* d_in, const int* in_sizes, int n_in,
                              void* d_out, int out_size)
{
    const float* x    = (const float*)d_in[0];
    const int*   mask = (const int*)d_in[1];
    const void*  scal = d_in[2];
    const float* Wq   = (const float*)d_in[3];
    const float* bq   = (const float*)d_in[4];
    const float* Wk   = (const float*)d_in[5];
    const float* bk   = (const float*)d_in[6];
    const float* Wv   = (const float*)d_in[7];
    const float* bv   = (const float*)d_in[8];
    float* out = (float*)d_out;

    dim3 g1(EMBED / BN, MTOT / BM, 3);
    qkv_gemm<<<g1, 256>>>(x, Wq, bq, Wk, bk, Wv, bv);

    cudaFuncSetAttribute(attn_kernel, cudaFuncAttributeMaxDynamicSharedMemorySize,
                         ATTN_SMEM_BYTES);
    dim3 g2(SEQ / 64, BATCH * NHEADS);
    attn_kernel<<<g2, 256, ATTN_SMEM_BYTES>>>(mask, scal, out);
}

// round 2
// speedup vs baseline: 1.6677x; 1.6677x over previous
#include <cuda_runtime.h>
#include <math.h>
#include <stdint.h>

#define EMBED   1024
#define NHEADS  16
#define HDIM    64
#define BATCH   2
#define SEQ     2048
#define MTOT    (BATCH*SEQ)
#define LOG2E   1.4426950408889634f

// ---------------- scratch (static device globals: allocation-guard legal) ---
__device__ float g_Q[(size_t)BATCH*NHEADS*SEQ*HDIM];
__device__ float g_K[(size_t)BATCH*NHEADS*SEQ*HDIM];
__device__ float g_V[(size_t)BATCH*NHEADS*SEQ*HDIM];

// ---------------- helpers ---------------------------------------------------
__device__ __forceinline__ unsigned f2tf(float f) {
    unsigned u;
    asm("cvt.rna.tf32.f32 %0, %1;" : "=r"(u) : "f"(f));
    return u;
}

__device__ __forceinline__ float ex2(float x) {
    float r;
    asm("ex2.approx.f32 %0, %1;" : "=f"(r) : "f"(x));
    return r;
}

// D = A(16x8,row) * B(8x8,col) + D   (tf32 inputs, f32 accum)
__device__ __forceinline__ void mma8(float* c, const unsigned* a, unsigned b0, unsigned b1) {
    asm volatile(
        "mma.sync.aligned.m16n8k8.row.col.f32.tf32.tf32.f32 "
        "{%0,%1,%2,%3},{%4,%5,%6,%7},{%8,%9},{%0,%1,%2,%3};\n"
        : "+f"(c[0]), "+f"(c[1]), "+f"(c[2]), "+f"(c[3])
        : "r"(a[0]), "r"(a[1]), "r"(a[2]), "r"(a[3]), "r"(b0), "r"(b1));
}

__device__ __forceinline__ void cp16(void* smem_dst, const void* gsrc) {
    unsigned s = (unsigned)__cvta_generic_to_shared(smem_dst);
    asm volatile("cp.async.cg.shared.global [%0], [%1], 16;\n" :: "r"(s), "l"(gsrc));
}
__device__ __forceinline__ void cp_commit() { asm volatile("cp.async.commit_group;\n"); }
__device__ __forceinline__ void cp_wait0()  { asm volatile("cp.async.wait_group 0;\n"); }

// robust scalar read: int32 / float32 / float64
__device__ __forceinline__ float load_scale(const void* p) {
    int iv = *(const int*)p;
    if (iv > 0 && iv < (1 << 20)) return (float)iv;
    float f = __int_as_float(iv);
    if (f > 1e-6f && f < 1e6f) return f;
    return (float)(*(const double*)p);
}

// ---------------- QKV projection GEMM (unchanged from round 1) ---------------
#define BM   128
#define BN   128
#define BKK  32
#define ASTR 36
#define BSTR 136

__global__ void __launch_bounds__(256, 2) qkv_gemm(
    const float* __restrict__ X,
    const float* __restrict__ Wq, const float* __restrict__ bq,
    const float* __restrict__ Wk, const float* __restrict__ bk,
    const float* __restrict__ Wv, const float* __restrict__ bv)
{
    __shared__ unsigned As[BM * ASTR];
    __shared__ unsigned Bs[BKK * BSTR];

    const float* W;
    const float* bias;
    float* Out;
    if (blockIdx.z == 0)      { W = Wq; bias = bq; Out = g_Q; }
    else if (blockIdx.z == 1) { W = Wk; bias = bk; Out = g_K; }
    else                      { W = Wv; bias = bv; Out = g_V; }

    const int tid  = threadIdx.x;
    const int lane = tid & 31, warp = tid >> 5;
    const int gid  = lane >> 2, tig = lane & 3;
    const int wm   = (warp >> 2) * 64;
    const int wn   = (warp & 3) * 32;
    const int mBase = blockIdx.y * BM;
    const int nBase = blockIdx.x * BN;

    float acc[4][4][4];
#pragma unroll
    for (int mt = 0; mt < 4; mt++)
#pragma unroll
        for (int nt = 0; nt < 4; nt++)
#pragma unroll
            for (int j = 0; j < 4; j++) acc[mt][nt][j] = 0.f;

    for (int kk = 0; kk < EMBED; kk += BKK) {
#pragma unroll
        for (int i = 0; i < 4; i++) {
            int idx = tid + i * 256;
            int r = idx >> 3, c = (idx & 7) * 4;
            float4 v = *(const float4*)(X + (size_t)(mBase + r) * EMBED + kk + c);
            unsigned* d = As + r * ASTR + c;
            d[0] = f2tf(v.x); d[1] = f2tf(v.y); d[2] = f2tf(v.z); d[3] = f2tf(v.w);
        }
#pragma unroll
        for (int i = 0; i < 4; i++) {
            int idx = tid + i * 256;
            int r = idx >> 5, c = (idx & 31) * 4;
            float4 v = *(const float4*)(W + (size_t)(kk + r) * EMBED + nBase + c);
            unsigned* d = Bs + r * BSTR + c;
            d[0] = f2tf(v.x); d[1] = f2tf(v.y); d[2] = f2tf(v.z); d[3] = f2tf(v.w);
        }
        __syncthreads();

#pragma unroll
        for (int ks = 0; ks < BKK; ks += 8) {
            unsigned a[4][4], bf[4][2];
#pragma unroll
            for (int mt = 0; mt < 4; mt++) {
                int r0 = wm + mt * 16;
                a[mt][0] = As[(r0 + gid)     * ASTR + ks + tig];
                a[mt][1] = As[(r0 + gid + 8) * ASTR + ks + tig];
                a[mt][2] = As[(r0 + gid)     * ASTR + ks + tig + 4];
                a[mt][3] = As[(r0 + gid + 8) * ASTR + ks + tig + 4];
            }
#pragma unroll
            for (int nt = 0; nt < 4; nt++) {
                int c0 = wn + nt * 8;
                bf[nt][0] = Bs[(ks + tig)     * BSTR + c0 + gid];
                bf[nt][1] = Bs[(ks + tig + 4) * BSTR + c0 + gid];
            }
#pragma unroll
            for (int mt = 0; mt < 4; mt++)
#pragma unroll
                for (int nt = 0; nt < 4; nt++)
                    mma8(acc[mt][nt], a[mt], bf[nt][0], bf[nt][1]);
        }
        __syncthreads();
    }

#pragma unroll
    for (int nt = 0; nt < 4; nt++) {
        int c0 = nBase + wn + nt * 8 + 2 * tig;
        float b0 = bias[c0], b1 = bias[c0 + 1];
        int h = c0 >> 6, d = c0 & 63;
#pragma unroll
        for (int mt = 0; mt < 4; mt++) {
#pragma unroll
            for (int rr = 0; rr < 2; rr++) {
                int r = mBase + wm + mt * 16 + gid + rr * 8;
                int bi = r >> 11, s = r & (SEQ - 1);
                float* op = Out + (((size_t)(bi * NHEADS + h) * SEQ + s) * HDIM) + d;
                op[0] = acc[mt][nt][rr * 2 + 0] + b0;
                op[1] = acc[mt][nt][rr * 2 + 1] + b1;
            }
        }
    }
}

// ---------------- flash attention v2 ------------------------------------------
// 4 warps, BQ=64, each warp: 16 rows x full 64 cols.
// Q frags + softmax state + O in registers. P never touches smem (V row-permuted).
#define KW 68        // K tile stride (conflict-free: 4*gid+tig)
#define VW 72        // V tile stride (conflict-free: 8*tig+gid)
#define TILE_K_WORDS (64*KW)
#define TILE_V_WORDS (64*VW)
#define ATTN_SMEM_BYTES (2*(TILE_K_WORDS + TILE_V_WORDS)*4)

__device__ __forceinline__ void stage_kv(const float* Kg, const float* Vg, int kt,
                                         float* Kd, float* Vd, int tid)
{
#pragma unroll
    for (int w = 0; w < 8; w++) {
        int c = tid + w * 128;           // 1024 chunks of 16B per tile
        int row = c >> 4, col = (c & 15) * 4;
        cp16(Kd + row * KW + col, Kg + (size_t)(kt + row) * HDIM + col);
        // sigma row permutation so S-accum regs serve as P A-frags in P@V
        int pr = (row & ~7) | (((row & 7) >> 1)) | ((row & 1) << 2);
        cp16(Vd + pr * VW + col, Vg + (size_t)(kt + row) * HDIM + col);
    }
}

__global__ void __launch_bounds__(128, 3) attn_kernel(
    const int* __restrict__ maskg, const void* __restrict__ scale_ptr,
    float* __restrict__ out)
{
    extern __shared__ float smem[];
    float* K0 = smem;
    float* V0 = K0 + TILE_K_WORDS;
    float* K1 = V0 + TILE_V_WORDS;
    float* V1 = K1 + TILE_K_WORDS;

    const int tid  = threadIdx.x;
    const int lane = tid & 31, warp = tid >> 5;
    const int gid  = lane >> 2, tig = lane & 3;
    const int wm   = warp * 16;

    const int bh = blockIdx.y;
    const int b  = bh >> 4;
    const int q0 = blockIdx.x * 64;

    const float* Qg = g_Q + (size_t)bh * SEQ * HDIM;
    const float* Kg = g_K + (size_t)bh * SEQ * HDIM;
    const float* Vg = g_V + (size_t)bh * SEQ * HDIM;
    const int* mrow = maskg + b * SEQ;

    const float rscale = 1.0f / load_scale(scale_ptr);

    // ---- stage Q (scaled, tf32) into K1 region, then lift frags to registers
    unsigned* Qs = (unsigned*)K1;
#pragma unroll
    for (int w = 0; w < 8; w++) {
        int c = tid + w * 128;
        int row = c >> 4, col = (c & 15) * 4;
        float4 v = *(const float4*)(Qg + (size_t)(q0 + row) * HDIM + col);
        uint4 u;
        u.x = f2tf(v.x * rscale); u.y = f2tf(v.y * rscale);
        u.z = f2tf(v.z * rscale); u.w = f2tf(v.w * rscale);
        *(uint4*)(Qs + row * KW + col) = u;
    }
    __syncthreads();

    unsigned q[8][4];
#pragma unroll
    for (int ks = 0; ks < 8; ks++) {
        q[ks][0] = Qs[(wm + gid)     * KW + 8*ks + tig];
        q[ks][1] = Qs[(wm + gid + 8) * KW + 8*ks + tig];
        q[ks][2] = Qs[(wm + gid)     * KW + 8*ks + tig + 4];
        q[ks][3] = Qs[(wm + gid + 8) * KW + 8*ks + tig + 4];
    }

    // issue first K/V tile (buf0)
    stage_kv(Kg, Vg, 0, K0, V0, tid);
    cp_commit();

    float o[8][4];
#pragma unroll
    for (int nt = 0; nt < 8; nt++)
#pragma unroll
        for (int j = 0; j < 4; j++) o[nt][j] = 0.f;
    float m0 = -1e30f, m1 = -1e30f, l0 = 0.f, l1 = 0.f;

    for (int kt = 0; kt < SEQ; kt += 64) {
        cp_wait0();
        __syncthreads();      // current tile visible to all; all done with other buf

        int cur = (kt >> 6) & 1;
        if (kt + 64 < SEQ) {  // prefetch next into the other buffer
            stage_kv(Kg, Vg, kt + 64, cur ? K0 : K1, cur ? V0 : V1, tid);
            cp_commit();
        }
        const unsigned* Ku = (const unsigned*)(cur ? K1 : K0);
        const unsigned* Vu = (const unsigned*)(cur ? V1 : V0);

        // mask bits (each warp computes its own ballot; broadcast LDGs are cheap)
        unsigned mb0 = __ballot_sync(0xffffffffu, mrow[kt + lane] != 0);
        unsigned mb1 = __ballot_sync(0xffffffffu, mrow[kt + 32 + lane] != 0);

        // ---- S = Q @ K^T  (16 x 64 per warp)
        float s[8][4];
#pragma unroll
        for (int nt = 0; nt < 8; nt++)
#pragma unroll
            for (int j = 0; j < 4; j++) s[nt][j] = 0.f;

#pragma unroll
        for (int ks = 0; ks < 8; ks++) {
#pragma unroll
            for (int nt = 0; nt < 8; nt++) {
                unsigned b0 = Ku[(8*nt + gid) * KW + 8*ks + tig];
                unsigned b1 = Ku[(8*nt + gid) * KW + 8*ks + tig + 4];
                mma8(s[nt], q[ks], b0, b1);
            }
        }

        // ---- mask
        if ((mb0 & mb1) != 0xffffffffu) {
#pragma unroll
            for (int nt = 0; nt < 8; nt++) {
                int col = 8*nt + 2*tig;
                unsigned mw = (nt < 4) ? mb0 : mb1;
                if (!((mw >> (col & 31)) & 1u))       { s[nt][0] = -1e30f; s[nt][2] = -1e30f; }
                if (!((mw >> ((col + 1) & 31)) & 1u)) { s[nt][1] = -1e30f; s[nt][3] = -1e30f; }
            }
        }

        // ---- row max (registers + quad shuffles; quad = one row)
        float rm0 = s[0][0], rm1 = s[0][2];
#pragma unroll
        for (int nt = 0; nt < 8; nt++) {
            rm0 = fmaxf(rm0, fmaxf(s[nt][0], s[nt][1]));
            rm1 = fmaxf(rm1, fmaxf(s[nt][2], s[nt][3]));
        }
        rm0 = fmaxf(rm0, __shfl_xor_sync(0xffffffffu, rm0, 1));
        rm0 = fmaxf(rm0, __shfl_xor_sync(0xffffffffu, rm0, 2));
        rm1 = fmaxf(rm1, __shfl_xor_sync(0xffffffffu, rm1, 1));
        rm1 = fmaxf(rm1, __shfl_xor_sync(0xffffffffu, rm1, 2));

        float m0n = fmaxf(m0, rm0), m1n = fmaxf(m1, rm1);
        float a0 = ex2((m0 - m0n) * LOG2E);
        float a1 = ex2((m1 - m1n) * LOG2E);
        m0 = m0n; m1 = m1n;

        // ---- p = exp(s - m), row sums
        float ls0 = 0.f, ls1 = 0.f;
#pragma unroll
        for (int nt = 0; nt < 8; nt++) {
            s[nt][0] = ex2((s[nt][0] - m0) * LOG2E);
            s[nt][1] = ex2((s[nt][1] - m0) * LOG2E);
            s[nt][2] = ex2((s[nt][2] - m1) * LOG2E);
            s[nt][3] = ex2((s[nt][3] - m1) * LOG2E);
            ls0 += s[nt][0] + s[nt][1];
            ls1 += s[nt][2] + s[nt][3];
        }
        ls0 += __shfl_xor_sync(0xffffffffu, ls0, 1);
        ls0 += __shfl_xor_sync(0xffffffffu, ls0, 2);
        ls1 += __shfl_xor_sync(0xffffffffu, ls1, 1);
        ls1 += __shfl_xor_sync(0xffffffffu, ls1, 2);
        l0 = l0 * a0 + ls0;
        l1 = l1 * a1 + ls1;

        // ---- rescale O, then O += P @ V (P A-frags straight from registers)
#pragma unroll
        for (int nt = 0; nt < 8; nt++) {
            o[nt][0] *= a0; o[nt][1] *= a0; o[nt][2] *= a1; o[nt][3] *= a1;
        }
#pragma unroll
        for (int g = 0; g < 8; g++) {
            unsigned a[4];
            a[0] = f2tf(s[g][0]);   // c0 -> A slot (row, tig)
            a[1] = f2tf(s[g][2]);   // c2 -> A slot (row+8, tig)
            a[2] = f2tf(s[g][1]);   // c1 -> A slot (row, tig+4)
            a[3] = f2tf(s[g][3]);   // c3 -> A slot (row+8, tig+4)
#pragma unroll
            for (int nt = 0; nt < 8; nt++) {
                unsigned b0 = Vu[(8*g + tig)     * VW + 8*nt + gid];
                unsigned b1 = Vu[(8*g + tig + 4) * VW + 8*nt + gid];
                mma8(o[nt], a, b0, b1);
            }
        }
    }

    // ---- epilogue: O / l
    float i0 = 1.f / l0, i1 = 1.f / l1;
    size_t r0base = ((size_t)bh * SEQ + q0 + wm + gid) * HDIM;
    size_t r1base = r0base + (size_t)8 * HDIM;
#pragma unroll
    for (int nt = 0; nt < 8; nt++) {
        int col = 8*nt + 2*tig;
        float2 v0 = { o[nt][0] * i0, o[nt][1] * i0 };
        float2 v1 = { o[nt][2] * i1, o[nt][3] * i1 };
        *(float2*)(out + r0base + col) = v0;
        *(float2*)(out + r1base + col) = v1;
    }
}

// ---------------- launcher ----------------------------------------------------
extern "C" void kernel_launch(void* const* d_in, const int* in_sizes, int n_in,
                              void* d_out, int out_size)
{
    const float* x    = (const float*)d_in[0];
    const int*   mask = (const int*)d_in[1];
    const void*  scal = d_in[2];
    const float* Wq   = (const float*)d_in[3];
    const float* bq   = (const float*)d_in[4];
    const float* Wk   = (const float*)d_in[5];
    const float* bk   = (const float*)d_in[6];
    const float* Wv   = (const float*)d_in[7];
    const float* bv   = (const float*)d_in[8];
    float* out = (float*)d_out;

    dim3 g1(EMBED / BN, MTOT / BM, 3);
    qkv_gemm<<<g1, 256>>>(x, Wq, bq, Wk, bk, Wv, bv);

    cudaFuncSetAttribute(attn_kernel, cudaFuncAttributeMaxDynamicSharedMemorySize,
                         ATTN_SMEM_BYTES);
    dim3 g2(SEQ / 64, BATCH * NHEADS);
    attn_kernel<<<g2, 128, ATTN_SMEM_BYTES>>>(mask, scal, out);
}